// round 12
// baseline (speedup 1.0000x reference)
#include <cuda_runtime.h>
#include <cstdint>

#define N_TOT 8192
#define D_DIM 512

// ---------------- scratch (static device globals: allocation-free) ----------
__device__ float g_Q[N_TOT * D_DIM];
__device__ float g_K[N_TOT * D_DIM];
__device__ float g_V[N_TOT * D_DIM];
__device__ float g_S[67108864];   // 8192 * 8192
__device__ float g_roff[N_TOT];

// ---------------- helpers ---------------------------------------------------
__device__ __forceinline__ float to_tf32(float x) {
    float r;
    asm("cvt.rna.tf32.f32 %0, %1;" : "=f"(r) : "f"(x));
    return r;
}

// 3xTF32 split: x = hi + lo with hi,lo in TF32; x - hi is exact in fp32.
__device__ __forceinline__ void split2(float x, uint32_t& hi, uint32_t& lo) {
    float h = to_tf32(x);
    float l = to_tf32(x - h);
    hi = __float_as_uint(h);
    lo = __float_as_uint(l);
}

__device__ __forceinline__ float fast_exp2(float x) {
    float y;
    asm("ex2.approx.ftz.f32 %0, %1;" : "=f"(y) : "f"(x));
    return y;
}

__device__ __forceinline__ void mma_tf32(float* c, const uint32_t* a, const uint32_t* b) {
    asm volatile(
        "mma.sync.aligned.m16n8k8.row.col.f32.tf32.tf32.f32 "
        "{%0,%1,%2,%3}, {%4,%5,%6,%7}, {%8,%9}, {%0,%1,%2,%3};\n"
        : "+f"(c[0]), "+f"(c[1]), "+f"(c[2]), "+f"(c[3])
        : "r"(a[0]), "r"(a[1]), "r"(a[2]), "r"(a[3]), "r"(b[0]), "r"(b[1]));
}

// ---------------- GEMM (3xTF32 effective-fp32 precision) --------------------
// MODE 0 (NN): C[M,N] = A[M,K] (row-major) @ B[K,N] (row-major)
// MODE 1 (NT): C[M,N] = A[M,K] (row-major) @ B[N,K]^T (B row-major [N,K])
// LEAKY: epilogue y = x>0 ? x : 0.01x
// SOFT : prologue on A: a' = exp2(a*log2e + rowoff[row])  (softmax-normalized P)
// CTA tile 128x128x32, 256 threads (8 warps of 64x32 warp tiles).
// SMEM tiles hold RAW fp32; hi/lo TF32 splits are computed in registers at
// fragment-load time; each logical MMA becomes 3 MMAs (hi*hi + hi*lo + lo*hi).
#define BM 128
#define BN 128
#define BK 32
#define AS_STRIDE 36     // 32 + 4 pad; 36*4B = 144B rows (16B aligned)
#define BS_STRIDE_NT 36
#define BS_STRIDE_NN 136 // 128 + 8 pad

template <int MODE, bool LEAKY, bool SOFT>
__global__ void __launch_bounds__(256, 2)
gemm_kernel(const float* __restrict__ A, const float* __restrict__ B,
            float* __restrict__ C, int M, int N, int K,
            const float* __restrict__ rowoff) {
    __shared__ float As[BM * AS_STRIDE];          // 4608 floats
    __shared__ float Bs[BM * AS_STRIDE];          // 4608 floats (>= 32*136)

    const int tid  = threadIdx.x;
    const int lane = tid & 31;
    const int warp = tid >> 5;
    const int wm   = warp >> 2;     // 0..1  (64-row slabs)
    const int wn   = warp & 3;      // 0..3  (32-col slabs)
    const int tg   = lane >> 2;     // groupID 0..7
    const int tig  = lane & 3;      // thread-in-group 0..3

    const int m0 = blockIdx.y * BM;
    const int n0 = blockIdx.x * BN;

    const float* Ablk = A + (size_t)m0 * K;
    const float* Bblk;
    if (MODE == 1) Bblk = B + (size_t)n0 * K;     // NT: rows of B are N
    else           Bblk = B + n0;                  // NN

    // softmax row offsets for this thread's 4 A-load rows (fixed across k-tiles)
    float soff[4];
    if (SOFT) {
#pragma unroll
        for (int i = 0; i < 4; i++)
            soff[i] = rowoff[m0 + ((tid + i * 256) >> 3)];
    }

    float acc[4][4][4];
#pragma unroll
    for (int a = 0; a < 4; a++)
#pragma unroll
        for (int b = 0; b < 4; b++)
#pragma unroll
            for (int c = 0; c < 4; c++) acc[a][b][c] = 0.f;

    const float L2E = 1.44269504088896f;

    for (int k0 = 0; k0 < K; k0 += BK) {
        __syncthreads();   // previous tile fully consumed

        // ---- stage A tile: 128 rows x 32 cols = 1024 float4 (raw fp32) ----
#pragma unroll
        for (int i = 0; i < 4; i++) {
            int f = tid + i * 256;
            int r = f >> 3, c4 = f & 7;
            float4 v = *(const float4*)(Ablk + (size_t)r * K + k0 + c4 * 4);
            if (SOFT) {
                v.x = fast_exp2(fmaf(v.x, L2E, soff[i]));
                v.y = fast_exp2(fmaf(v.y, L2E, soff[i]));
                v.z = fast_exp2(fmaf(v.z, L2E, soff[i]));
                v.w = fast_exp2(fmaf(v.w, L2E, soff[i]));
            }
            *(float4*)(&As[r * AS_STRIDE + c4 * 4]) = v;
        }

        // ---- stage B tile (raw fp32) ----
        if (MODE == 1) {   // NT: 128 rows (n) x 32 cols (k)
#pragma unroll
            for (int i = 0; i < 4; i++) {
                int f = tid + i * 256;
                int r = f >> 3, c4 = f & 7;
                float4 v = *(const float4*)(Bblk + (size_t)r * K + k0 + c4 * 4);
                *(float4*)(&Bs[r * BS_STRIDE_NT + c4 * 4]) = v;
            }
        } else {           // NN: 32 rows (k) x 128 cols (n)
#pragma unroll
            for (int i = 0; i < 4; i++) {
                int f = tid + i * 256;
                int r = f >> 5, c4 = f & 31;
                float4 v = *(const float4*)(Bblk + (size_t)(k0 + r) * N + c4 * 4);
                *(float4*)(&Bs[r * BS_STRIDE_NN + c4 * 4]) = v;
            }
        }
        __syncthreads();

        // ---- compute: 4 k-steps of 8, 3xTF32 per logical MMA ----
#pragma unroll
        for (int kk = 0; kk < 4; kk++) {
            const int k8 = kk * 8;

            // B fragments: split into hi/lo
            uint32_t bh[4][2], bl[4][2];
#pragma unroll
            for (int nt = 0; nt < 4; nt++) {
                int col = wn * 32 + nt * 8 + tg;
                float b0, b1;
                if (MODE == 1) {
                    const float* p = &Bs[col * BS_STRIDE_NT + k8 + tig];
                    b0 = p[0]; b1 = p[4];
                } else {
                    b0 = Bs[(k8 + tig)     * BS_STRIDE_NN + col];
                    b1 = Bs[(k8 + 4 + tig) * BS_STRIDE_NN + col];
                }
                split2(b0, bh[nt][0], bl[nt][0]);
                split2(b1, bh[nt][1], bl[nt][1]);
            }

#pragma unroll
            for (int mt = 0; mt < 4; mt++) {
                int row = wm * 64 + mt * 16 + tg;
                const float* p = &As[row * AS_STRIDE + k8 + tig];
                float a0 = p[0];
                float a1 = p[8 * AS_STRIDE];
                float a2 = p[4];
                float a3 = p[8 * AS_STRIDE + 4];
                uint32_t ah[4], al[4];
                split2(a0, ah[0], al[0]);
                split2(a1, ah[1], al[1]);
                split2(a2, ah[2], al[2]);
                split2(a3, ah[3], al[3]);
#pragma unroll
                for (int nt = 0; nt < 4; nt++) {
                    mma_tf32(acc[mt][nt], al, bh[nt]);   // lo*hi
                    mma_tf32(acc[mt][nt], ah, bl[nt]);   // hi*lo
                    mma_tf32(acc[mt][nt], ah, bh[nt]);   // hi*hi
                }
            }
        }
    }

    // ---- epilogue ----
    float* Cblk = C + (size_t)(m0 + wm * 64) * N + n0 + wn * 32;
#pragma unroll
    for (int mt = 0; mt < 4; mt++) {
#pragma unroll
        for (int nt = 0; nt < 4; nt++) {
            int r = mt * 16 + tg;
            int c = nt * 8 + 2 * tig;
            float v0 = acc[mt][nt][0], v1 = acc[mt][nt][1];
            float v2 = acc[mt][nt][2], v3 = acc[mt][nt][3];
            if (LEAKY) {
                v0 = v0 > 0.f ? v0 : 0.01f * v0;
                v1 = v1 > 0.f ? v1 : 0.01f * v1;
                v2 = v2 > 0.f ? v2 : 0.01f * v2;
                v3 = v3 > 0.f ? v3 : 0.01f * v3;
            }
            *(float2*)(Cblk + (size_t)r * N + c)       = make_float2(v0, v1);
            *(float2*)(Cblk + (size_t)(r + 8) * N + c) = make_float2(v2, v3);
        }
    }
}

// ---------------- row stats: rowoff = -(max*log2e + log2(sum exp)) ----------
__global__ void rowstats_kernel(const float* __restrict__ S, float* __restrict__ roff) {
    __shared__ float red[8];
    const int row = blockIdx.x;
    const int tid = threadIdx.x;
    const float* p = S + (size_t)row * N_TOT;
    const float L2E = 1.44269504088896f;

    float v[32];
    float m = -3.402823e38f;
#pragma unroll
    for (int i = 0; i < 32; i++) {
        v[i] = p[tid + (i << 8)];
        m = fmaxf(m, v[i]);
    }
#pragma unroll
    for (int o = 16; o; o >>= 1) m = fmaxf(m, __shfl_xor_sync(0xffffffffu, m, o));
    if ((tid & 31) == 0) red[tid >> 5] = m;
    __syncthreads();
    m = red[0];
#pragma unroll
    for (int w = 1; w < 8; w++) m = fmaxf(m, red[w]);
    __syncthreads();

    float s = 0.f;
#pragma unroll
    for (int i = 0; i < 32; i++) s += fast_exp2((v[i] - m) * L2E);
#pragma unroll
    for (int o = 16; o; o >>= 1) s += __shfl_xor_sync(0xffffffffu, s, o);
    if ((tid & 31) == 0) red[tid >> 5] = s;
    __syncthreads();
    if (tid == 0) {
        float tot = 0.f;
#pragma unroll
        for (int w = 0; w < 8; w++) tot += red[w];
        roff[row] = -(m * L2E + __log2f(tot));
    }
}

// ---------------- launch -----------------------------------------------------
extern "C" void kernel_launch(void* const* d_in, const int* in_sizes, int n_in,
                              void* d_out, int out_size) {
    const float* x1 = (const float*)d_in[0];
    const float* x2 = (const float*)d_in[1];
    const float* wq = (const float*)d_in[2];
    const float* wk = (const float*)d_in[3];
    const float* wv = (const float*)d_in[4];
    float* out = (float*)d_out;

    float *Q, *Kp, *V, *S, *roff;
    cudaGetSymbolAddress((void**)&Q,    g_Q);
    cudaGetSymbolAddress((void**)&Kp,   g_K);
    cudaGetSymbolAddress((void**)&V,    g_V);
    cudaGetSymbolAddress((void**)&S,    g_S);
    cudaGetSymbolAddress((void**)&roff, g_roff);

    dim3 blk(256);
    dim3 gproj(D_DIM / BN, N_TOT / BM);   // (4, 64)
    dim3 glog(N_TOT / BN, N_TOT / BM);    // (64, 64)

    // 1. projections (3xTF32 => effectively fp32)
    gemm_kernel<0, false, false><<<gproj, blk>>>(x1, wq, Q,  N_TOT, D_DIM, D_DIM, nullptr);
    gemm_kernel<0, false, false><<<gproj, blk>>>(x2, wk, Kp, N_TOT, D_DIM, D_DIM, nullptr);
    gemm_kernel<0, false, false><<<gproj, blk>>>(x1, wv, V,  N_TOT, D_DIM, D_DIM, nullptr);
    // 2. logits S = leaky(Q @ K^T)
    gemm_kernel<1, true, false><<<glog, blk>>>(Q, Kp, S, N_TOT, N_TOT, D_DIM, nullptr);
    // 3. per-row softmax stats
    rowstats_kernel<<<N_TOT, 256>>>(S, roff);
    // 4. out = softmax(S) @ V   (exp fused into A-tile staging)
    gemm_kernel<0, false, true><<<gproj, blk>>>(S, V, out, N_TOT, D_DIM, N_TOT, roff);
}

// round 13
// speedup vs baseline: 1.2890x; 1.2890x over previous
#include <cuda_runtime.h>
#include <cstdint>

#define N_TOT 8192
#define D_DIM 512

// ---------------- scratch (static device globals: allocation-free) ----------
__device__ float g_Q[N_TOT * D_DIM];
__device__ float g_K[N_TOT * D_DIM];
__device__ float g_V[N_TOT * D_DIM];
__device__ float g_S[67108864];   // 8192 * 8192
__device__ float g_roff[N_TOT];

// ---------------- helpers ---------------------------------------------------
__device__ __forceinline__ float to_tf32(float x) {
    float r;
    asm("cvt.rna.tf32.f32 %0, %1;" : "=f"(r) : "f"(x));
    return r;
}

__device__ __forceinline__ float fast_exp2(float x) {
    float y;
    asm("ex2.approx.ftz.f32 %0, %1;" : "=f"(y) : "f"(x));
    return y;
}

__device__ __forceinline__ void mma_tf32(float* c, const uint32_t* a, const uint32_t* b) {
    asm volatile(
        "mma.sync.aligned.m16n8k8.row.col.f32.tf32.tf32.f32 "
        "{%0,%1,%2,%3}, {%4,%5,%6,%7}, {%8,%9}, {%0,%1,%2,%3};\n"
        : "+f"(c[0]), "+f"(c[1]), "+f"(c[2]), "+f"(c[3])
        : "r"(a[0]), "r"(a[1]), "r"(a[2]), "r"(a[3]), "r"(b[0]), "r"(b[1]));
}

// ---------------- GEMM (split-precision TF32, hi/lo staged in SMEM) ---------
// MODE 0 (NN): C[M,N] = A[M,K] (row-major) @ B[K,N] (row-major)
// MODE 1 (NT): C[M,N] = A[M,K] (row-major) @ B[N,K]^T (B row-major [N,K])
// LEAKY: epilogue y = x>0 ? x : 0.01x
// SOFT : prologue on A: a' = exp2(a*log2e + rowoff[row])  (softmax-normalized P)
// NMMA : 3 -> al*bh + ah*bl + ah*bh (effective fp32)
//        2 -> al*bh + ah*bh         (A exact-split, B rounded to tf32)
// CTA tile 128x128x32, 256 threads (8 warps of 64x32 warp tiles).
// hi/lo TF32 splits are computed ONCE at staging time and stored in SMEM
// (dynamic, 72KB/CTA for NMMA=3) so the inner loop issues only LDS + MMA.
#define BM 128
#define BN 128
#define BK 32
#define AS_STRIDE 36     // 32 + 4 pad; conflict-free for the fragment pattern
#define BS_STRIDE_NT 36
#define BS_STRIDE_NN 136 // 128 + 8 pad

#define TILE_F 4608      // floats per tile buffer (128*36; >= 32*136)

template <int MODE, bool LEAKY, bool SOFT, int NMMA>
__global__ void __launch_bounds__(256, 2)
gemm_kernel(const float* __restrict__ A, const float* __restrict__ B,
            float* __restrict__ C, int M, int N, int K,
            const float* __restrict__ rowoff) {
    extern __shared__ float smem[];
    float* As_h = smem;
    float* As_l = smem + TILE_F;
    float* Bs_h = smem + 2 * TILE_F;
    float* Bs_l = smem + 3 * TILE_F;   // only present when NMMA == 3

    const int tid  = threadIdx.x;
    const int lane = tid & 31;
    const int warp = tid >> 5;
    const int wm   = warp >> 2;     // 0..1  (64-row slabs)
    const int wn   = warp & 3;      // 0..3  (32-col slabs)
    const int tg   = lane >> 2;     // groupID 0..7
    const int tig  = lane & 3;      // thread-in-group 0..3

    const int m0 = blockIdx.y * BM;
    const int n0 = blockIdx.x * BN;

    const float* Ablk = A + (size_t)m0 * K;
    const float* Bblk;
    if (MODE == 1) Bblk = B + (size_t)n0 * K;     // NT: rows of B are N
    else           Bblk = B + n0;                  // NN

    // softmax row offsets for this thread's 4 A-load rows (fixed across k-tiles)
    float soff[4];
    if (SOFT) {
#pragma unroll
        for (int i = 0; i < 4; i++)
            soff[i] = rowoff[m0 + ((tid + i * 256) >> 3)];
    }

    float acc[4][4][4];
#pragma unroll
    for (int a = 0; a < 4; a++)
#pragma unroll
        for (int b = 0; b < 4; b++)
#pragma unroll
            for (int c = 0; c < 4; c++) acc[a][b][c] = 0.f;

    const float L2E = 1.44269504088896f;

    for (int k0 = 0; k0 < K; k0 += BK) {
        __syncthreads();   // previous tile fully consumed

        // ---- stage A tile: 128 rows x 32 cols, split hi/lo ----
#pragma unroll
        for (int i = 0; i < 4; i++) {
            int f = tid + i * 256;
            int r = f >> 3, c4 = f & 7;
            float4 v = *(const float4*)(Ablk + (size_t)r * K + k0 + c4 * 4);
            if (SOFT) {
                v.x = fast_exp2(fmaf(v.x, L2E, soff[i]));
                v.y = fast_exp2(fmaf(v.y, L2E, soff[i]));
                v.z = fast_exp2(fmaf(v.z, L2E, soff[i]));
                v.w = fast_exp2(fmaf(v.w, L2E, soff[i]));
            }
            float4 h, l;
            h.x = to_tf32(v.x); l.x = to_tf32(v.x - h.x);
            h.y = to_tf32(v.y); l.y = to_tf32(v.y - h.y);
            h.z = to_tf32(v.z); l.z = to_tf32(v.z - h.z);
            h.w = to_tf32(v.w); l.w = to_tf32(v.w - h.w);
            *(float4*)(&As_h[r * AS_STRIDE + c4 * 4]) = h;
            *(float4*)(&As_l[r * AS_STRIDE + c4 * 4]) = l;
        }

        // ---- stage B tile: hi (+lo if NMMA==3) ----
        if (MODE == 1) {   // NT: 128 rows (n) x 32 cols (k)
#pragma unroll
            for (int i = 0; i < 4; i++) {
                int f = tid + i * 256;
                int r = f >> 3, c4 = f & 7;
                float4 v = *(const float4*)(Bblk + (size_t)r * K + k0 + c4 * 4);
                float4 h;
                h.x = to_tf32(v.x); h.y = to_tf32(v.y);
                h.z = to_tf32(v.z); h.w = to_tf32(v.w);
                *(float4*)(&Bs_h[r * BS_STRIDE_NT + c4 * 4]) = h;
                if (NMMA == 3) {
                    float4 l;
                    l.x = to_tf32(v.x - h.x); l.y = to_tf32(v.y - h.y);
                    l.z = to_tf32(v.z - h.z); l.w = to_tf32(v.w - h.w);
                    *(float4*)(&Bs_l[r * BS_STRIDE_NT + c4 * 4]) = l;
                }
            }
        } else {           // NN: 32 rows (k) x 128 cols (n)
#pragma unroll
            for (int i = 0; i < 4; i++) {
                int f = tid + i * 256;
                int r = f >> 5, c4 = f & 31;
                float4 v = *(const float4*)(Bblk + (size_t)(k0 + r) * N + c4 * 4);
                float4 h;
                h.x = to_tf32(v.x); h.y = to_tf32(v.y);
                h.z = to_tf32(v.z); h.w = to_tf32(v.w);
                *(float4*)(&Bs_h[r * BS_STRIDE_NN + c4 * 4]) = h;
                if (NMMA == 3) {
                    float4 l;
                    l.x = to_tf32(v.x - h.x); l.y = to_tf32(v.y - h.y);
                    l.z = to_tf32(v.z - h.z); l.w = to_tf32(v.w - h.w);
                    *(float4*)(&Bs_l[r * BS_STRIDE_NN + c4 * 4]) = l;
                }
            }
        }
        __syncthreads();

        // ---- compute: 4 k-steps of 8; LDS + MMA only ----
#pragma unroll
        for (int kk = 0; kk < 4; kk++) {
            const int k8 = kk * 8;

            uint32_t bh[4][2], bl[4][2];
#pragma unroll
            for (int nt = 0; nt < 4; nt++) {
                int col = wn * 32 + nt * 8 + tg;
                if (MODE == 1) {
                    int off = col * BS_STRIDE_NT + k8 + tig;
                    bh[nt][0] = __float_as_uint(Bs_h[off]);
                    bh[nt][1] = __float_as_uint(Bs_h[off + 4]);
                    if (NMMA == 3) {
                        bl[nt][0] = __float_as_uint(Bs_l[off]);
                        bl[nt][1] = __float_as_uint(Bs_l[off + 4]);
                    }
                } else {
                    int off0 = (k8 + tig)     * BS_STRIDE_NN + col;
                    int off1 = (k8 + 4 + tig) * BS_STRIDE_NN + col;
                    bh[nt][0] = __float_as_uint(Bs_h[off0]);
                    bh[nt][1] = __float_as_uint(Bs_h[off1]);
                    if (NMMA == 3) {
                        bl[nt][0] = __float_as_uint(Bs_l[off0]);
                        bl[nt][1] = __float_as_uint(Bs_l[off1]);
                    }
                }
            }

#pragma unroll
            for (int mt = 0; mt < 4; mt++) {
                int off = (wm * 64 + mt * 16 + tg) * AS_STRIDE + k8 + tig;
                uint32_t ah[4], al[4];
                ah[0] = __float_as_uint(As_h[off]);
                ah[1] = __float_as_uint(As_h[off + 8 * AS_STRIDE]);
                ah[2] = __float_as_uint(As_h[off + 4]);
                ah[3] = __float_as_uint(As_h[off + 8 * AS_STRIDE + 4]);
                al[0] = __float_as_uint(As_l[off]);
                al[1] = __float_as_uint(As_l[off + 8 * AS_STRIDE]);
                al[2] = __float_as_uint(As_l[off + 4]);
                al[3] = __float_as_uint(As_l[off + 8 * AS_STRIDE + 4]);
#pragma unroll
                for (int nt = 0; nt < 4; nt++) {
                    mma_tf32(acc[mt][nt], al, bh[nt]);                 // lo*hi
                    if (NMMA == 3) mma_tf32(acc[mt][nt], ah, bl[nt]);  // hi*lo
                    mma_tf32(acc[mt][nt], ah, bh[nt]);                 // hi*hi
                }
            }
        }
    }

    // ---- epilogue ----
    float* Cblk = C + (size_t)(m0 + wm * 64) * N + n0 + wn * 32;
#pragma unroll
    for (int mt = 0; mt < 4; mt++) {
#pragma unroll
        for (int nt = 0; nt < 4; nt++) {
            int r = mt * 16 + tg;
            int c = nt * 8 + 2 * tig;
            float v0 = acc[mt][nt][0], v1 = acc[mt][nt][1];
            float v2 = acc[mt][nt][2], v3 = acc[mt][nt][3];
            if (LEAKY) {
                v0 = v0 > 0.f ? v0 : 0.01f * v0;
                v1 = v1 > 0.f ? v1 : 0.01f * v1;
                v2 = v2 > 0.f ? v2 : 0.01f * v2;
                v3 = v3 > 0.f ? v3 : 0.01f * v3;
            }
            *(float2*)(Cblk + (size_t)r * N + c)       = make_float2(v0, v1);
            *(float2*)(Cblk + (size_t)(r + 8) * N + c) = make_float2(v2, v3);
        }
    }
}

// ---------------- row stats: rowoff = -(max*log2e + log2(sum exp)) ----------
__global__ void rowstats_kernel(const float* __restrict__ S, float* __restrict__ roff) {
    __shared__ float red[8];
    const int row = blockIdx.x;
    const int tid = threadIdx.x;
    const float* p = S + (size_t)row * N_TOT;
    const float L2E = 1.44269504088896f;

    float v[32];
    float m = -3.402823e38f;
#pragma unroll
    for (int i = 0; i < 32; i++) {
        v[i] = p[tid + (i << 8)];
        m = fmaxf(m, v[i]);
    }
#pragma unroll
    for (int o = 16; o; o >>= 1) m = fmaxf(m, __shfl_xor_sync(0xffffffffu, m, o));
    if ((tid & 31) == 0) red[tid >> 5] = m;
    __syncthreads();
    m = red[0];
#pragma unroll
    for (int w = 1; w < 8; w++) m = fmaxf(m, red[w]);
    __syncthreads();

    float s = 0.f;
#pragma unroll
    for (int i = 0; i < 32; i++) s += fast_exp2((v[i] - m) * L2E);
#pragma unroll
    for (int o = 16; o; o >>= 1) s += __shfl_xor_sync(0xffffffffu, s, o);
    if ((tid & 31) == 0) red[tid >> 5] = s;
    __syncthreads();
    if (tid == 0) {
        float tot = 0.f;
#pragma unroll
        for (int w = 0; w < 8; w++) tot += red[w];
        roff[row] = -(m * L2E + __log2f(tot));
    }
}

// ---------------- launch -----------------------------------------------------
extern "C" void kernel_launch(void* const* d_in, const int* in_sizes, int n_in,
                              void* d_out, int out_size) {
    const float* x1 = (const float*)d_in[0];
    const float* x2 = (const float*)d_in[1];
    const float* wq = (const float*)d_in[2];
    const float* wk = (const float*)d_in[3];
    const float* wv = (const float*)d_in[4];
    float* out = (float*)d_out;

    float *Q, *Kp, *V, *S, *roff;
    cudaGetSymbolAddress((void**)&Q,    g_Q);
    cudaGetSymbolAddress((void**)&Kp,   g_K);
    cudaGetSymbolAddress((void**)&V,    g_V);
    cudaGetSymbolAddress((void**)&S,    g_S);
    cudaGetSymbolAddress((void**)&roff, g_roff);

    constexpr int SMEM3 = 4 * TILE_F * 4;   // 73728 B (A hi/lo + B hi/lo)
    constexpr int SMEM2 = 3 * TILE_F * 4;   // 55296 B (A hi/lo + B hi)

    cudaFuncSetAttribute(gemm_kernel<0, false, false, 3>,
                         cudaFuncAttributeMaxDynamicSharedMemorySize, SMEM3);
    cudaFuncSetAttribute(gemm_kernel<1, true, false, 3>,
                         cudaFuncAttributeMaxDynamicSharedMemorySize, SMEM3);
    cudaFuncSetAttribute(gemm_kernel<0, false, true, 2>,
                         cudaFuncAttributeMaxDynamicSharedMemorySize, SMEM2);

    dim3 blk(256);
    dim3 gproj(D_DIM / BN, N_TOT / BM);   // (4, 64)
    dim3 glog(N_TOT / BN, N_TOT / BM);    // (64, 64)

    // 1. projections (3xTF32 => effectively fp32)
    gemm_kernel<0, false, false, 3><<<gproj, blk, SMEM3>>>(x1, wq, Q,  N_TOT, D_DIM, D_DIM, nullptr);
    gemm_kernel<0, false, false, 3><<<gproj, blk, SMEM3>>>(x2, wk, Kp, N_TOT, D_DIM, D_DIM, nullptr);
    gemm_kernel<0, false, false, 3><<<gproj, blk, SMEM3>>>(x1, wv, V,  N_TOT, D_DIM, D_DIM, nullptr);
    // 2. logits S = leaky(Q @ K^T)  (3xTF32: logit ABSOLUTE error is sensitive)
    gemm_kernel<1, true, false, 3><<<glog, blk, SMEM3>>>(Q, Kp, S, N_TOT, N_TOT, D_DIM, nullptr);
    // 3. per-row softmax stats
    rowstats_kernel<<<N_TOT, 256>>>(S, roff);
    // 4. out = softmax(S) @ V   (exp fused into A staging; 2xTF32: P exact-split, V~tf32)
    gemm_kernel<0, false, true, 2><<<gproj, blk, SMEM2>>>(S, V, out, N_TOT, D_DIM, N_TOT, roff);
}